// round 1
// baseline (speedup 1.0000x reference)
#include <cuda_runtime.h>
#include <cstdint>

// ---------------------------------------------------------------------------
// GCN_VCG: 3-iteration bipartite message passing.
//   per iter: 4 two-layer MLPs (d=128), 4 degree-normalized segment sums over
//   Eh=315000 edges, 2 update GEMMs (concat[3*128] @ [384,128]).
// Outputs: stacked v_embs [4,V,128] then c_embs [4,C,128] in d_out.
// ---------------------------------------------------------------------------

#define D        128
#define TM       64
#define NTHREADS 256

#define VMAX  50000
#define CMAX  210000
#define EHMAX 315000

// ------------------------- scratch (no runtime alloc) ----------------------
__device__ float g_t_pv2c[(size_t)VMAX * D];
__device__ float g_t_nv2c[(size_t)VMAX * D];
__device__ float g_t_pc2v[(size_t)CMAX * D];
__device__ float g_t_nc2v[(size_t)CMAX * D];
__device__ float g_agg_c[2][(size_t)CMAX * D];   // [0]=pos, [1]=neg aggregates -> c
__device__ float g_agg_v[2][(size_t)VMAX * D];   // [0]=pos, [1]=neg aggregates -> v
__device__ float g_pv_deg[VMAX];
__device__ float g_nv_deg[VMAX];
__device__ float g_pc_deg[CMAX];
__device__ float g_nc_deg[CMAX];
__device__ float g_p_inv[EHMAX];
__device__ float g_n_inv[EHMAX];
__device__ int   g_p_v[EHMAX];
__device__ int   g_p_c[EHMAX];
__device__ int   g_n_v[EHMAX];
__device__ int   g_n_c[EHMAX];

// ------------------------------- helpers -----------------------------------
__device__ __forceinline__ void load_tile(const float* __restrict__ src, float* Xs,
                                          int row0, int N, int tid) {
    // TM*D/4 = 2048 float4 loads, 256 threads -> 8 iterations, fully coalesced
#pragma unroll
    for (int i = tid; i < TM * D / 4; i += NTHREADS) {
        int r  = i >> 5;        // D/4 = 32 float4 per row
        int c4 = i & 31;
        float4 v;
        int g = row0 + r;
        if (g < N)
            v = *reinterpret_cast<const float4*>(src + (size_t)g * D + c4 * 4);
        else
            v = make_float4(0.f, 0.f, 0.f, 0.f);
        *reinterpret_cast<float4*>(Xs + r * D + c4 * 4) = v;
    }
}

__device__ __forceinline__ void load_w(const float* __restrict__ W, float* Ws, int tid) {
#pragma unroll
    for (int i = tid; i < D * D / 4; i += NTHREADS)
        reinterpret_cast<float4*>(Ws)[i] = reinterpret_cast<const float4*>(W)[i];
}

// 64x128 tile GEMM: acc[8][4] micro-tile per thread; Xs reads are warp
// broadcasts (same row/col for all lanes), Ws reads are conflict-free LDS.128.
__device__ __forceinline__ void tile_gemm(const float* Xs, const float* Ws,
                                          float acc[8][4], int tx, int ty) {
    const float* xbase = Xs + (ty * 8) * D;
#pragma unroll 8
    for (int k = 0; k < D; k++) {
        const float4 w = *reinterpret_cast<const float4*>(Ws + k * D + tx * 4);
#pragma unroll
        for (int r = 0; r < 8; r++) {
            float xv = xbase[r * D + k];
            acc[r][0] = fmaf(xv, w.x, acc[r][0]);
            acc[r][1] = fmaf(xv, w.y, acc[r][1]);
            acc[r][2] = fmaf(xv, w.z, acc[r][2]);
            acc[r][3] = fmaf(xv, w.w, acc[r][3]);
        }
    }
}

// ------------------------------ GEMM kernels --------------------------------
// Two-layer MLP: Y = relu(X@W0 + b0) @ W1 + b1.   W = [2,128,128], b = [2,128]
extern "C" __global__ void __launch_bounds__(NTHREADS)
mlp2_kernel(const float* __restrict__ X, const float* __restrict__ W,
            const float* __restrict__ bias, float* __restrict__ Y, int N) {
    extern __shared__ float sm[];
    float* Xs = sm;                 // TM*D
    float* Ws = sm + TM * D;        // D*D
    float* Bs = Ws + D * D;         // D
    const int tid = threadIdx.x, tx = tid & 31, ty = tid >> 5;
    const int row0 = blockIdx.x * TM;

    load_tile(X, Xs, row0, N, tid);
    load_w(W, Ws, tid);
    if (tid < D) Bs[tid] = bias[tid];
    __syncthreads();

    float acc[8][4];
#pragma unroll
    for (int r = 0; r < 8; r++)
#pragma unroll
        for (int j = 0; j < 4; j++) acc[r][j] = 0.f;

    tile_gemm(Xs, Ws, acc, tx, ty);

    // bias + relu (read bias BEFORE it is overwritten for layer 2)
    const float4 b0 = *reinterpret_cast<const float4*>(Bs + tx * 4);
#pragma unroll
    for (int r = 0; r < 8; r++) {
        acc[r][0] = fmaxf(acc[r][0] + b0.x, 0.f);
        acc[r][1] = fmaxf(acc[r][1] + b0.y, 0.f);
        acc[r][2] = fmaxf(acc[r][2] + b0.z, 0.f);
        acc[r][3] = fmaxf(acc[r][3] + b0.w, 0.f);
    }
    __syncthreads();   // all threads finished reading Xs/Ws/Bs

    // write hidden into Xs; load layer-2 weights
#pragma unroll
    for (int r = 0; r < 8; r++) {
        float4 h = make_float4(acc[r][0], acc[r][1], acc[r][2], acc[r][3]);
        *reinterpret_cast<float4*>(Xs + (ty * 8 + r) * D + tx * 4) = h;
    }
    load_w(W + D * D, Ws, tid);
    if (tid < D) Bs[tid] = bias[D + tid];
    __syncthreads();

#pragma unroll
    for (int r = 0; r < 8; r++)
#pragma unroll
        for (int j = 0; j < 4; j++) acc[r][j] = 0.f;

    tile_gemm(Xs, Ws, acc, tx, ty);

    const float4 b1 = *reinterpret_cast<const float4*>(Bs + tx * 4);
#pragma unroll
    for (int r = 0; r < 8; r++) {
        int g = row0 + ty * 8 + r;
        if (g < N) {
            float4 o = make_float4(acc[r][0] + b1.x, acc[r][1] + b1.y,
                                   acc[r][2] + b1.z, acc[r][3] + b1.w);
            *reinterpret_cast<float4*>(Y + (size_t)g * D + tx * 4) = o;
        }
    }
}

// Update: Y = [X0|X1|X2] @ W(384x128) + b
extern "C" __global__ void __launch_bounds__(NTHREADS)
update_kernel(const float* __restrict__ X0, const float* __restrict__ X1,
              const float* __restrict__ X2, const float* __restrict__ W,
              const float* __restrict__ bias, float* __restrict__ Y, int N) {
    extern __shared__ float sm[];
    float* Xs = sm;
    float* Ws = sm + TM * D;
    const int tid = threadIdx.x, tx = tid & 31, ty = tid >> 5;
    const int row0 = blockIdx.x * TM;

    float acc[8][4];
#pragma unroll
    for (int r = 0; r < 8; r++)
#pragma unroll
        for (int j = 0; j < 4; j++) acc[r][j] = 0.f;

    const float* srcs[3] = {X0, X1, X2};
#pragma unroll
    for (int s = 0; s < 3; s++) {
        if (s) __syncthreads();
        load_tile(srcs[s], Xs, row0, N, tid);
        load_w(W + (size_t)s * D * D, Ws, tid);
        __syncthreads();
        tile_gemm(Xs, Ws, acc, tx, ty);
    }

    const float4 bb = *reinterpret_cast<const float4*>(bias + tx * 4);
#pragma unroll
    for (int r = 0; r < 8; r++) {
        int g = row0 + ty * 8 + r;
        if (g < N) {
            float4 o = make_float4(acc[r][0] + bb.x, acc[r][1] + bb.y,
                                   acc[r][2] + bb.z, acc[r][3] + bb.w);
            *reinterpret_cast<float4*>(Y + (size_t)g * D + tx * 4) = o;
        }
    }
}

// ------------------------------ graph prep ----------------------------------
extern "C" __global__ void degree_kernel(const int* __restrict__ vE,
                                         const int* __restrict__ cE,
                                         const int* __restrict__ pE,
                                         const int* __restrict__ nE, int Eh) {
    int t = blockIdx.x * blockDim.x + threadIdx.x;
    if (t < Eh) {
        int e = pE[t];
        atomicAdd(&g_pv_deg[vE[e]], 1.f);
        atomicAdd(&g_pc_deg[cE[e]], 1.f);
    } else if (t < 2 * Eh) {
        int e = nE[t - Eh];
        atomicAdd(&g_nv_deg[vE[e]], 1.f);
        atomicAdd(&g_nc_deg[cE[e]], 1.f);
    }
}

extern "C" __global__ void edge_prep_kernel(const int* __restrict__ vE,
                                            const int* __restrict__ cE,
                                            const int* __restrict__ pE,
                                            const int* __restrict__ nE, int Eh) {
    int t = blockIdx.x * blockDim.x + threadIdx.x;
    if (t < Eh) {
        int e = pE[t];
        int v = vE[e], c = cE[e];
        g_p_v[t] = v;
        g_p_c[t] = c;
        float dv = fmaxf(g_pv_deg[v], 1.f);
        float dc = fmaxf(g_pc_deg[c], 1.f);
        g_p_inv[t] = rsqrtf(dv * dc);
    } else if (t < 2 * Eh) {
        int i = t - Eh;
        int e = nE[i];
        int v = vE[e], c = cE[e];
        g_n_v[i] = v;
        g_n_c[i] = c;
        float dv = fmaxf(g_nv_deg[v], 1.f);
        float dc = fmaxf(g_nc_deg[c], 1.f);
        g_n_inv[i] = rsqrtf(dv * dc);
    }
}

// ------------------------------ segment sum ---------------------------------
// One warp per edge; each lane handles a float4 chunk. Vector RED halves-plus
// the LSU issue count vs 4 scalar atomics.
extern "C" __global__ void __launch_bounds__(NTHREADS)
scatter_kernel(const float* __restrict__ src, float* __restrict__ dst,
               const int* __restrict__ sidx, const int* __restrict__ didx,
               const float* __restrict__ inv, int Eh) {
    long t = (long)blockIdx.x * blockDim.x + threadIdx.x;
    int e = (int)(t >> 5);
    int lane = (int)(t & 31);
    if (e >= Eh) return;
    int s = sidx[e];
    int d = didx[e];
    float w = inv[e];
    float4 v = *reinterpret_cast<const float4*>(src + (size_t)s * D + lane * 4);
    v.x *= w; v.y *= w; v.z *= w; v.w *= w;
    float* p = dst + (size_t)d * D + lane * 4;
    asm volatile("red.global.add.v4.f32 [%0], {%1,%2,%3,%4};"
                 :: "l"(p), "f"(v.x), "f"(v.y), "f"(v.z), "f"(v.w)
                 : "memory");
}

// -------------------------------- launch ------------------------------------
extern "C" void kernel_launch(void* const* d_in, const int* in_sizes, int n_in,
                              void* d_out, int out_size) {
    // Input order (metadata): v_size, c_size, v_edge_index, c_edge_index,
    // p_edge_index, n_edge_index, v_emb, c_emb, {pv2c,nv2c,pc2v,nc2v}_{W,b},
    // cu_W, cu_b, vu_W, vu_b.  If scalar ints were dropped, shift base.
    int base = (n_in >= 20) ? 2 : 0;
    const int*   v_edge = (const int*)d_in[base + 0];
    const int*   c_edge = (const int*)d_in[base + 1];
    const int*   p_edge = (const int*)d_in[base + 2];
    const int*   n_edge = (const int*)d_in[base + 3];
    const float* v0     = (const float*)d_in[base + 4];
    const float* c0     = (const float*)d_in[base + 5];
    const float* Wm[4], *Bm[4];
    for (int i = 0; i < 4; i++) {
        Wm[i] = (const float*)d_in[base + 6 + 2 * i];
        Bm[i] = (const float*)d_in[base + 7 + 2 * i];
    }
    const float* cuW = (const float*)d_in[base + 14];
    const float* cub = (const float*)d_in[base + 15];
    const float* vuW = (const float*)d_in[base + 16];
    const float* vub = (const float*)d_in[base + 17];

    const int Eh = in_sizes[base + 2];
    const int V  = in_sizes[base + 4] / D;
    const int C  = in_sizes[base + 5] / D;

    // scratch symbol addresses
    void *p;
    float *t_pv2c, *t_nv2c, *t_pc2v, *t_nc2v, *agg_c, *agg_v;
    float *pvdeg, *nvdeg, *pcdeg, *ncdeg, *pinv, *ninv;
    int *pvi, *pci, *nvi, *nci;
    cudaGetSymbolAddress(&p, g_t_pv2c); t_pv2c = (float*)p;
    cudaGetSymbolAddress(&p, g_t_nv2c); t_nv2c = (float*)p;
    cudaGetSymbolAddress(&p, g_t_pc2v); t_pc2v = (float*)p;
    cudaGetSymbolAddress(&p, g_t_nc2v); t_nc2v = (float*)p;
    cudaGetSymbolAddress(&p, g_agg_c);  agg_c  = (float*)p;
    cudaGetSymbolAddress(&p, g_agg_v);  agg_v  = (float*)p;
    cudaGetSymbolAddress(&p, g_pv_deg); pvdeg  = (float*)p;
    cudaGetSymbolAddress(&p, g_nv_deg); nvdeg  = (float*)p;
    cudaGetSymbolAddress(&p, g_pc_deg); pcdeg  = (float*)p;
    cudaGetSymbolAddress(&p, g_nc_deg); ncdeg  = (float*)p;
    cudaGetSymbolAddress(&p, g_p_inv);  pinv   = (float*)p;
    cudaGetSymbolAddress(&p, g_n_inv);  ninv   = (float*)p;
    cudaGetSymbolAddress(&p, g_p_v);    pvi    = (int*)p;
    cudaGetSymbolAddress(&p, g_p_c);    pci    = (int*)p;
    cudaGetSymbolAddress(&p, g_n_v);    nvi    = (int*)p;
    cudaGetSymbolAddress(&p, g_n_c);    nci    = (int*)p;

    float* agg_c_p = agg_c;
    float* agg_c_n = agg_c + (size_t)CMAX * D;
    float* agg_v_p = agg_v;
    float* agg_v_n = agg_v + (size_t)VMAX * D;

    float* outv = (float*)d_out;                   // [4][V][D]
    float* outc = outv + (size_t)4 * V * D;        // [4][C][D]
    const size_t vbytes = (size_t)V * D * sizeof(float);
    const size_t cbytes = (size_t)C * D * sizeof(float);

    const size_t smem = (size_t)(TM * D + D * D + D) * sizeof(float);
    cudaFuncSetAttribute(mlp2_kernel, cudaFuncAttributeMaxDynamicSharedMemorySize, (int)smem);
    cudaFuncSetAttribute(update_kernel, cudaFuncAttributeMaxDynamicSharedMemorySize, (int)smem);

    // ---- degree + per-edge norm prep (iteration-invariant) ----
    cudaMemsetAsync(pvdeg, 0, (size_t)V * sizeof(float));
    cudaMemsetAsync(nvdeg, 0, (size_t)V * sizeof(float));
    cudaMemsetAsync(pcdeg, 0, (size_t)C * sizeof(float));
    cudaMemsetAsync(ncdeg, 0, (size_t)C * sizeof(float));
    {
        int blk = (2 * Eh + NTHREADS - 1) / NTHREADS;
        degree_kernel<<<blk, NTHREADS>>>(v_edge, c_edge, p_edge, n_edge, Eh);
        edge_prep_kernel<<<blk, NTHREADS>>>(v_edge, c_edge, p_edge, n_edge, Eh);
    }

    // ---- slot 0 of outputs = initial embeddings ----
    cudaMemcpyAsync(outv, v0, vbytes, cudaMemcpyDeviceToDevice);
    cudaMemcpyAsync(outc, c0, cbytes, cudaMemcpyDeviceToDevice);

    const int vtiles = (V + TM - 1) / TM;
    const int ctiles = (C + TM - 1) / TM;
    const int sblocks = (int)(((long)Eh * 32 + NTHREADS - 1) / NTHREADS);

    for (int t = 0; t < 3; t++) {
        const float* vin = outv + (size_t)t * V * D;
        const float* cin = outc + (size_t)t * C * D;
        float* vout = outv + (size_t)(t + 1) * V * D;
        float* cout = outc + (size_t)(t + 1) * C * D;

        // 4 two-layer MLPs on the pre-update embeddings
        mlp2_kernel<<<vtiles, NTHREADS, smem>>>(vin, Wm[0], Bm[0], t_pv2c, V);
        mlp2_kernel<<<vtiles, NTHREADS, smem>>>(vin, Wm[1], Bm[1], t_nv2c, V);
        mlp2_kernel<<<ctiles, NTHREADS, smem>>>(cin, Wm[2], Bm[2], t_pc2v, C);
        mlp2_kernel<<<ctiles, NTHREADS, smem>>>(cin, Wm[3], Bm[3], t_nc2v, C);

        // zero aggregate buffers
        cudaMemsetAsync(agg_c, 0, (size_t)2 * CMAX * D * sizeof(float));
        cudaMemsetAsync(agg_v, 0, (size_t)2 * VMAX * D * sizeof(float));

        // 4 normalized segment sums (edge-parallel vector RED)
        scatter_kernel<<<sblocks, NTHREADS>>>(t_pv2c, agg_c_p, pvi, pci, pinv, Eh);
        scatter_kernel<<<sblocks, NTHREADS>>>(t_nv2c, agg_c_n, nvi, nci, ninv, Eh);
        scatter_kernel<<<sblocks, NTHREADS>>>(t_pc2v, agg_v_p, pci, pvi, pinv, Eh);
        scatter_kernel<<<sblocks, NTHREADS>>>(t_nc2v, agg_v_n, nci, nvi, ninv, Eh);

        // updates: concat @ W(384x128) + b
        update_kernel<<<ctiles, NTHREADS, smem>>>(cin, agg_c_p, agg_c_n, cuW, cub, cout, C);
        update_kernel<<<vtiles, NTHREADS, smem>>>(vin, agg_v_p, agg_v_n, vuW, vub, vout, V);
    }
}

// round 3
// speedup vs baseline: 1.4194x; 1.4194x over previous
#include <cuda_runtime.h>
#include <cuda_bf16.h>
#include <cstdint>

// ---------------------------------------------------------------------------
// GCN_VCG via mma.sync bf16 (HMMA) with 2-term float split:
//   A@B = Ah@Bh + Al@Bh + Ah@Bl   (fp32 accumulate in registers)
// Weight images pre-split to bf16 hi/lo and pre-swizzled once per launch.
// (tcgen05 is unavailable: harness compiles through compute_103 virtual arch.)
// ---------------------------------------------------------------------------

#define D        128
#define NT       256
#define VMAX     50000
#define CMAX     210000
#define EHMAX    315000

// smem layout (bytes): four 128x128 bf16 tiles, each 32KB, XOR-swizzled
#define SM_AHI   0
#define SM_ALO   32768
#define SM_WHI   65536
#define SM_WLO   98304
#define SM_TOTAL 131072

// ------------------------- scratch (no runtime alloc) ----------------------
__device__ float g_t_pv2c[(size_t)VMAX * D];
__device__ float g_t_nv2c[(size_t)VMAX * D];
__device__ float g_t_pc2v[(size_t)CMAX * D];
__device__ float g_t_nc2v[(size_t)CMAX * D];
__device__ float g_agg_c[2][(size_t)CMAX * D];
__device__ float g_agg_v[2][(size_t)VMAX * D];
__device__ float g_pv_deg[VMAX];
__device__ float g_nv_deg[VMAX];
__device__ float g_pc_deg[CMAX];
__device__ float g_nc_deg[CMAX];
__device__ float g_p_inv[EHMAX];
__device__ float g_n_inv[EHMAX];
__device__ int   g_p_v[EHMAX];
__device__ int   g_p_c[EHMAX];
__device__ int   g_n_v[EHMAX];
__device__ int   g_n_c[EHMAX];
// weight images: per layer/chunk: [hi 32KB | lo 32KB], swizzled, smem-ready
__device__ unsigned char g_wimg_mlp[4][2 * 65536];
__device__ unsigned char g_wimg_cu[3 * 65536];
__device__ unsigned char g_wimg_vu[3 * 65536];

// ------------------------------ helpers ------------------------------------
__device__ __forceinline__ uint32_t smem_u32(const void* p) {
    uint32_t a;
    asm("{ .reg .u64 t; cvta.to.shared.u64 t, %1; cvt.u32.u64 %0, t; }"
        : "=r"(a) : "l"(p));
    return a;
}

// byte offset of bf16 element (row r, col c) in a 128x128 bf16 tile,
// 256B rows = 16 chunks of 16B, chunk XOR-swizzled by (r&7) for
// conflict-free ldmatrix column access.
__device__ __host__ __forceinline__ uint32_t swz(int r, int c) {
    return ((uint32_t)r << 8) + ((uint32_t)(((c >> 3) ^ (r & 7)) & 15) << 4)
         + ((uint32_t)(c & 7) << 1);
}

__device__ __forceinline__ void split2(float a, float b, uint32_t& hi, uint32_t& lo) {
    __nv_bfloat16 ha = __float2bfloat16(a);
    __nv_bfloat16 hb = __float2bfloat16(b);
    __nv_bfloat16 la = __float2bfloat16(a - __bfloat162float(ha));
    __nv_bfloat16 lb = __float2bfloat16(b - __bfloat162float(hb));
    hi = (uint32_t)__bfloat16_as_ushort(ha) | ((uint32_t)__bfloat16_as_ushort(hb) << 16);
    lo = (uint32_t)__bfloat16_as_ushort(la) | ((uint32_t)__bfloat16_as_ushort(lb) << 16);
}

__device__ __forceinline__ void ldm4(uint32_t addr, uint32_t& d0, uint32_t& d1,
                                     uint32_t& d2, uint32_t& d3) {
    asm volatile("ldmatrix.sync.aligned.m8n8.x4.shared.b16 {%0,%1,%2,%3}, [%4];"
                 : "=r"(d0), "=r"(d1), "=r"(d2), "=r"(d3) : "r"(addr));
}

__device__ __forceinline__ void mma16816(float* c, const uint32_t* a,
                                         const uint32_t* b) {
    asm volatile(
        "mma.sync.aligned.m16n8k16.row.col.f32.bf16.bf16.f32 "
        "{%0,%1,%2,%3}, {%4,%5,%6,%7}, {%8,%9}, {%0,%1,%2,%3};"
        : "+f"(c[0]), "+f"(c[1]), "+f"(c[2]), "+f"(c[3])
        : "r"(a[0]), "r"(a[1]), "r"(a[2]), "r"(a[3]), "r"(b[0]), "r"(b[1]));
}

// One K=128 GEMM pass over the CTA tile: acc[s][nt][4] for warp tile 32mx64n.
__device__ __forceinline__ void gemm_pass(uint32_t sA, uint32_t sW,
                                          float acc[2][8][4], int wid, int lane) {
    const int wm = wid & 3, wn = wid >> 2;
#pragma unroll
    for (int ks = 0; ks < 8; ks++) {
        const int kc = ks * 2;
        uint32_t a[2][4];
#pragma unroll
        for (int s = 0; s < 2; s++) {
            int row = wm * 32 + s * 16 + (lane & 7) + ((lane >> 3) & 1) * 8;
            int chunk = ((kc + (lane >> 4)) ^ (row & 7)) & 15;
            ldm4(sA + row * 256 + chunk * 16, a[s][0], a[s][1], a[s][2], a[s][3]);
        }
        uint32_t b[8][2];
#pragma unroll
        for (int p = 0; p < 4; p++) {
            int row = wn * 64 + p * 16 + (lane & 7) + (lane >> 4) * 8;
            int chunk = ((kc + ((lane >> 3) & 1)) ^ (row & 7)) & 15;
            ldm4(sW + row * 256 + chunk * 16,
                 b[2 * p][0], b[2 * p][1], b[2 * p + 1][0], b[2 * p + 1][1]);
        }
#pragma unroll
        for (int s = 0; s < 2; s++)
#pragma unroll
            for (int nt = 0; nt < 8; nt++)
                mma16816(acc[s][nt], a[s], b[nt]);
    }
}

// load 128-row fp32 tile, split to bf16 hi/lo into swizzled smem tiles
__device__ __forceinline__ void load_split_tile(const float* __restrict__ X,
                                                char* sm, int row0, int N, int tid) {
#pragma unroll 4
    for (int i = tid; i < 4096; i += NT) {
        int r = i >> 5, c4 = i & 31;
        int g = row0 + r;
        float4 x = make_float4(0.f, 0.f, 0.f, 0.f);
        if (g < N) x = *reinterpret_cast<const float4*>(X + (size_t)g * D + c4 * 4);
        uint32_t h0, l0, h1, l1;
        split2(x.x, x.y, h0, l0);
        split2(x.z, x.w, h1, l1);
        uint32_t off = swz(r, c4 * 4);   // 8B-aligned (c4*4 & 7 in {0,4})
        *reinterpret_cast<uint2*>(sm + SM_AHI + off) = make_uint2(h0, h1);
        *reinterpret_cast<uint2*>(sm + SM_ALO + off) = make_uint2(l0, l1);
    }
}

__device__ __forceinline__ void copy_w(const uint4* __restrict__ src, char* sm, int tid) {
#pragma unroll 4
    for (int i = tid; i < 4096; i += NT)     // 64KB: hi tile + lo tile contiguous
        reinterpret_cast<uint4*>(sm + SM_WHI)[i] = src[i];
}

__device__ __forceinline__ void zero_acc(float acc[2][8][4]) {
#pragma unroll
    for (int s = 0; s < 2; s++)
#pragma unroll
        for (int nt = 0; nt < 8; nt++)
#pragma unroll
            for (int j = 0; j < 4; j++) acc[s][nt][j] = 0.f;
}

__device__ __forceinline__ void split_passes(uint32_t sb, float acc[2][8][4],
                                             int wid, int lane) {
    gemm_pass(sb + SM_AHI, sb + SM_WHI, acc, wid, lane);
    gemm_pass(sb + SM_ALO, sb + SM_WHI, acc, wid, lane);
    gemm_pass(sb + SM_AHI, sb + SM_WLO, acc, wid, lane);
}

// ------------------------------ GEMM kernels --------------------------------
// Two-layer MLP, fused: Y = relu(X@W0+b0)@W1 + b1
extern "C" __global__ void __launch_bounds__(NT, 1)
mlp2_mma_kernel(const float* __restrict__ X, const uint4* __restrict__ Wimg,
                const float* __restrict__ bias, float* __restrict__ Y, int N) {
    extern __shared__ char sm[];
    const uint32_t sb = smem_u32(sm);
    const int tid = threadIdx.x, wid = tid >> 5, lane = tid & 31;
    const int row0 = blockIdx.x * 128;
    const int wm = wid & 3, wn = wid >> 2;

    load_split_tile(X, sm, row0, N, tid);
    copy_w(Wimg, sm, tid);
    __syncthreads();

    float acc[2][8][4];
    zero_acc(acc);
    split_passes(sb, acc, wid, lane);
    __syncthreads();                          // done reading A / W tiles

    // epilogue 1: bias + relu, split hidden back into A tiles (k dim = n)
#pragma unroll
    for (int s = 0; s < 2; s++) {
#pragma unroll
        for (int nt = 0; nt < 8; nt++) {
            int m = wm * 32 + s * 16 + (lane >> 2);
            int n = wn * 64 + nt * 8 + (lane & 3) * 2;
            float b0 = __ldg(bias + n), b1 = __ldg(bias + n + 1);
            float v0 = fmaxf(acc[s][nt][0] + b0, 0.f);
            float v1 = fmaxf(acc[s][nt][1] + b1, 0.f);
            uint32_t h, l;
            split2(v0, v1, h, l);
            uint32_t off = swz(m, n);
            *reinterpret_cast<uint32_t*>(sm + SM_AHI + off) = h;
            *reinterpret_cast<uint32_t*>(sm + SM_ALO + off) = l;
            v0 = fmaxf(acc[s][nt][2] + b0, 0.f);
            v1 = fmaxf(acc[s][nt][3] + b1, 0.f);
            split2(v0, v1, h, l);
            off = swz(m + 8, n);
            *reinterpret_cast<uint32_t*>(sm + SM_AHI + off) = h;
            *reinterpret_cast<uint32_t*>(sm + SM_ALO + off) = l;
        }
    }
    copy_w(Wimg + 4096, sm, tid);             // layer-2 weights
    __syncthreads();

    zero_acc(acc);
    split_passes(sb, acc, wid, lane);

    // epilogue 2: bias + store fp32
    const float* b2 = bias + D;
#pragma unroll
    for (int s = 0; s < 2; s++) {
#pragma unroll
        for (int nt = 0; nt < 8; nt++) {
            int m = wm * 32 + s * 16 + (lane >> 2);
            int n = wn * 64 + nt * 8 + (lane & 3) * 2;
            float b0 = __ldg(b2 + n), b1 = __ldg(b2 + n + 1);
            int g0 = row0 + m, g1 = row0 + m + 8;
            if (g0 < N) {
                float2 o = make_float2(acc[s][nt][0] + b0, acc[s][nt][1] + b1);
                *reinterpret_cast<float2*>(Y + (size_t)g0 * D + n) = o;
            }
            if (g1 < N) {
                float2 o = make_float2(acc[s][nt][2] + b0, acc[s][nt][3] + b1);
                *reinterpret_cast<float2*>(Y + (size_t)g1 * D + n) = o;
            }
        }
    }
}

// Update: Y = [X0|X1|X2] @ W(384x128) + b   (3 K-chunks of 128)
extern "C" __global__ void __launch_bounds__(NT, 1)
update_mma_kernel(const float* __restrict__ X0, const float* __restrict__ X1,
                  const float* __restrict__ X2, const uint4* __restrict__ Wimg,
                  const float* __restrict__ bias, float* __restrict__ Y, int N) {
    extern __shared__ char sm[];
    const uint32_t sb = smem_u32(sm);
    const int tid = threadIdx.x, wid = tid >> 5, lane = tid & 31;
    const int row0 = blockIdx.x * 128;
    const int wm = wid & 3, wn = wid >> 2;

    float acc[2][8][4];
    zero_acc(acc);

    const float* srcs[3] = {X0, X1, X2};
#pragma unroll
    for (int s = 0; s < 3; s++) {
        if (s) __syncthreads();               // previous pass done reading smem
        load_split_tile(srcs[s], sm, row0, N, tid);
        copy_w(Wimg + s * 4096, sm, tid);
        __syncthreads();
        split_passes(sb, acc, wid, lane);
    }

#pragma unroll
    for (int s = 0; s < 2; s++) {
#pragma unroll
        for (int nt = 0; nt < 8; nt++) {
            int m = wm * 32 + s * 16 + (lane >> 2);
            int n = wn * 64 + nt * 8 + (lane & 3) * 2;
            float b0 = __ldg(bias + n), b1 = __ldg(bias + n + 1);
            int g0 = row0 + m, g1 = row0 + m + 8;
            if (g0 < N) {
                float2 o = make_float2(acc[s][nt][0] + b0, acc[s][nt][1] + b1);
                *reinterpret_cast<float2*>(Y + (size_t)g0 * D + n) = o;
            }
            if (g1 < N) {
                float2 o = make_float2(acc[s][nt][2] + b0, acc[s][nt][3] + b1);
                *reinterpret_cast<float2*>(Y + (size_t)g1 * D + n) = o;
            }
        }
    }
}

// ----------------------- weight image conversion ----------------------------
// W[l][k][n] (x@W layout) -> per layer: swizzled [n][k] bf16 hi(32KB)|lo(32KB)
extern "C" __global__ void wconv_mlp_kernel(const float* __restrict__ W,
                                            unsigned char* __restrict__ img) {
    int t = blockIdx.x * blockDim.x + threadIdx.x;
    if (t >= 2 * 128 * 128) return;
    int l = t >> 14, k = (t >> 7) & 127, n = t & 127;
    float w = W[t];
    __nv_bfloat16 h = __float2bfloat16(w);
    __nv_bfloat16 lo = __float2bfloat16(w - __bfloat162float(h));
    unsigned char* base = img + (size_t)l * 65536;
    uint32_t off = swz(n, k);
    *reinterpret_cast<__nv_bfloat16*>(base + off) = h;
    *reinterpret_cast<__nv_bfloat16*>(base + 32768 + off) = lo;
}

extern "C" __global__ void wconv_upd_kernel(const float* __restrict__ W,
                                            unsigned char* __restrict__ img) {
    int t = blockIdx.x * blockDim.x + threadIdx.x;
    if (t >= 384 * 128) return;
    int k = t >> 7, n = t & 127;
    int s = k >> 7, kl = k & 127;
    float w = W[t];
    __nv_bfloat16 h = __float2bfloat16(w);
    __nv_bfloat16 lo = __float2bfloat16(w - __bfloat162float(h));
    unsigned char* base = img + (size_t)s * 65536;
    uint32_t off = swz(n, kl);
    *reinterpret_cast<__nv_bfloat16*>(base + off) = h;
    *reinterpret_cast<__nv_bfloat16*>(base + 32768 + off) = lo;
}

// ------------------------------ graph prep ----------------------------------
extern "C" __global__ void degree_kernel(const int* __restrict__ vE,
                                         const int* __restrict__ cE,
                                         const int* __restrict__ pE,
                                         const int* __restrict__ nE, int Eh) {
    int t = blockIdx.x * blockDim.x + threadIdx.x;
    if (t < Eh) {
        int e = pE[t];
        atomicAdd(&g_pv_deg[vE[e]], 1.f);
        atomicAdd(&g_pc_deg[cE[e]], 1.f);
    } else if (t < 2 * Eh) {
        int e = nE[t - Eh];
        atomicAdd(&g_nv_deg[vE[e]], 1.f);
        atomicAdd(&g_nc_deg[cE[e]], 1.f);
    }
}

extern "C" __global__ void edge_prep_kernel(const int* __restrict__ vE,
                                            const int* __restrict__ cE,
                                            const int* __restrict__ pE,
                                            const int* __restrict__ nE, int Eh) {
    int t = blockIdx.x * blockDim.x + threadIdx.x;
    if (t < Eh) {
        int e = pE[t];
        int v = vE[e], c = cE[e];
        g_p_v[t] = v;
        g_p_c[t] = c;
        g_p_inv[t] = rsqrtf(fmaxf(g_pv_deg[v], 1.f) * fmaxf(g_pc_deg[c], 1.f));
    } else if (t < 2 * Eh) {
        int i = t - Eh;
        int e = nE[i];
        int v = vE[e], c = cE[e];
        g_n_v[i] = v;
        g_n_c[i] = c;
        g_n_inv[i] = rsqrtf(fmaxf(g_nv_deg[v], 1.f) * fmaxf(g_nc_deg[c], 1.f));
    }
}

// ------------------------------ segment sum ---------------------------------
extern "C" __global__ void __launch_bounds__(NT)
scatter_kernel(const float* __restrict__ src, float* __restrict__ dst,
               const int* __restrict__ sidx, const int* __restrict__ didx,
               const float* __restrict__ inv, int Eh) {
    long t = (long)blockIdx.x * blockDim.x + threadIdx.x;
    int e = (int)(t >> 5);
    int lane = (int)(t & 31);
    if (e >= Eh) return;
    int s = sidx[e];
    int d = didx[e];
    float w = inv[e];
    float4 v = *reinterpret_cast<const float4*>(src + (size_t)s * D + lane * 4);
    v.x *= w; v.y *= w; v.z *= w; v.w *= w;
    float* p = dst + (size_t)d * D + lane * 4;
    asm volatile("red.global.add.v4.f32 [%0], {%1,%2,%3,%4};"
                 :: "l"(p), "f"(v.x), "f"(v.y), "f"(v.z), "f"(v.w)
                 : "memory");
}

// -------------------------------- launch ------------------------------------
extern "C" void kernel_launch(void* const* d_in, const int* in_sizes, int n_in,
                              void* d_out, int out_size) {
    int base = (n_in >= 20) ? 2 : 0;
    const int*   v_edge = (const int*)d_in[base + 0];
    const int*   c_edge = (const int*)d_in[base + 1];
    const int*   p_edge = (const int*)d_in[base + 2];
    const int*   n_edge = (const int*)d_in[base + 3];
    const float* v0     = (const float*)d_in[base + 4];
    const float* c0     = (const float*)d_in[base + 5];
    const float *Wm[4], *Bm[4];
    for (int i = 0; i < 4; i++) {
        Wm[i] = (const float*)d_in[base + 6 + 2 * i];
        Bm[i] = (const float*)d_in[base + 7 + 2 * i];
    }
    const float* cuW = (const float*)d_in[base + 14];
    const float* cub = (const float*)d_in[base + 15];
    const float* vuW = (const float*)d_in[base + 16];
    const float* vub = (const float*)d_in[base + 17];

    const int Eh = in_sizes[base + 2];
    const int V  = in_sizes[base + 4] / D;
    const int C  = in_sizes[base + 5] / D;

    void* p;
    float *t_pv2c, *t_nv2c, *t_pc2v, *t_nc2v, *agg_c, *agg_v;
    float *pvdeg, *nvdeg, *pcdeg, *ncdeg, *pinv, *ninv;
    int *pvi, *pci, *nvi, *nci;
    unsigned char *img_mlp, *img_cu, *img_vu;
    cudaGetSymbolAddress(&p, g_t_pv2c); t_pv2c = (float*)p;
    cudaGetSymbolAddress(&p, g_t_nv2c); t_nv2c = (float*)p;
    cudaGetSymbolAddress(&p, g_t_pc2v); t_pc2v = (float*)p;
    cudaGetSymbolAddress(&p, g_t_nc2v); t_nc2v = (float*)p;
    cudaGetSymbolAddress(&p, g_agg_c);  agg_c  = (float*)p;
    cudaGetSymbolAddress(&p, g_agg_v);  agg_v  = (float*)p;
    cudaGetSymbolAddress(&p, g_pv_deg); pvdeg  = (float*)p;
    cudaGetSymbolAddress(&p, g_nv_deg); nvdeg  = (float*)p;
    cudaGetSymbolAddress(&p, g_pc_deg); pcdeg  = (float*)p;
    cudaGetSymbolAddress(&p, g_nc_deg); ncdeg  = (float*)p;
    cudaGetSymbolAddress(&p, g_p_inv);  pinv   = (float*)p;
    cudaGetSymbolAddress(&p, g_n_inv);  ninv   = (float*)p;
    cudaGetSymbolAddress(&p, g_p_v);    pvi    = (int*)p;
    cudaGetSymbolAddress(&p, g_p_c);    pci    = (int*)p;
    cudaGetSymbolAddress(&p, g_n_v);    nvi    = (int*)p;
    cudaGetSymbolAddress(&p, g_n_c);    nci    = (int*)p;
    cudaGetSymbolAddress(&p, g_wimg_mlp); img_mlp = (unsigned char*)p;
    cudaGetSymbolAddress(&p, g_wimg_cu);  img_cu  = (unsigned char*)p;
    cudaGetSymbolAddress(&p, g_wimg_vu);  img_vu  = (unsigned char*)p;

    float* agg_c_p = agg_c;
    float* agg_c_n = agg_c + (size_t)CMAX * D;
    float* agg_v_p = agg_v;
    float* agg_v_n = agg_v + (size_t)VMAX * D;

    float* outv = (float*)d_out;
    float* outc = outv + (size_t)4 * V * D;

    cudaFuncSetAttribute(mlp2_mma_kernel,
                         cudaFuncAttributeMaxDynamicSharedMemorySize, SM_TOTAL);
    cudaFuncSetAttribute(update_mma_kernel,
                         cudaFuncAttributeMaxDynamicSharedMemorySize, SM_TOTAL);

    // ---- prep: degrees, per-edge norms, weight images ----
    cudaMemsetAsync(pvdeg, 0, (size_t)V * sizeof(float));
    cudaMemsetAsync(nvdeg, 0, (size_t)V * sizeof(float));
    cudaMemsetAsync(pcdeg, 0, (size_t)C * sizeof(float));
    cudaMemsetAsync(ncdeg, 0, (size_t)C * sizeof(float));
    {
        int blk = (2 * Eh + NT - 1) / NT;
        degree_kernel<<<blk, NT>>>(v_edge, c_edge, p_edge, n_edge, Eh);
        edge_prep_kernel<<<blk, NT>>>(v_edge, c_edge, p_edge, n_edge, Eh);
    }
    for (int i = 0; i < 4; i++)
        wconv_mlp_kernel<<<128, 256>>>(Wm[i], img_mlp + (size_t)i * 2 * 65536);
    wconv_upd_kernel<<<192, 256>>>(cuW, img_cu);
    wconv_upd_kernel<<<192, 256>>>(vuW, img_vu);

    cudaMemcpyAsync(outv, v0, (size_t)V * D * sizeof(float), cudaMemcpyDeviceToDevice);
    cudaMemcpyAsync(outc, c0, (size_t)C * D * sizeof(float), cudaMemcpyDeviceToDevice);

    const int vtiles = (V + 127) / 128;
    const int ctiles = (C + 127) / 128;
    const int sblocks = (int)(((long)Eh * 32 + NT - 1) / NT);

    for (int t = 0; t < 3; t++) {
        const float* vin = outv + (size_t)t * V * D;
        const float* cin = outc + (size_t)t * C * D;
        float* vout = outv + (size_t)(t + 1) * V * D;
        float* cout = outc + (size_t)(t + 1) * C * D;

        mlp2_mma_kernel<<<vtiles, NT, SM_TOTAL>>>(
            vin, (const uint4*)(img_mlp + 0 * 2 * 65536), Bm[0], t_pv2c, V);
        mlp2_mma_kernel<<<vtiles, NT, SM_TOTAL>>>(
            vin, (const uint4*)(img_mlp + 1 * 2 * 65536), Bm[1], t_nv2c, V);
        mlp2_mma_kernel<<<ctiles, NT, SM_TOTAL>>>(
            cin, (const uint4*)(img_mlp + 2 * 2 * 65536), Bm[2], t_pc2v, C);
        mlp2_mma_kernel<<<ctiles, NT, SM_TOTAL>>>(
            cin, (const uint4*)(img_mlp + 3 * 2 * 65536), Bm[3], t_nc2v, C);

        cudaMemsetAsync(agg_c, 0, (size_t)2 * CMAX * D * sizeof(float));
        cudaMemsetAsync(agg_v, 0, (size_t)2 * VMAX * D * sizeof(float));

        scatter_kernel<<<sblocks, NT>>>(t_pv2c, agg_c_p, pvi, pci, pinv, Eh);
        scatter_kernel<<<sblocks, NT>>>(t_nv2c, agg_c_n, nvi, nci, ninv, Eh);
        scatter_kernel<<<sblocks, NT>>>(t_pc2v, agg_v_p, pci, pvi, pinv, Eh);
        scatter_kernel<<<sblocks, NT>>>(t_nc2v, agg_v_n, nci, nvi, ninv, Eh);

        update_mma_kernel<<<ctiles, NT, SM_TOTAL>>>(
            cin, agg_c_p, agg_c_n, (const uint4*)img_cu, cub, cout, C);
        update_mma_kernel<<<vtiles, NT, SM_TOTAL>>>(
            vin, agg_v_p, agg_v_n, (const uint4*)img_vu, vub, vout, V);
    }
}

// round 4
// speedup vs baseline: 1.6055x; 1.1312x over previous
#include <cuda_runtime.h>
#include <cuda_bf16.h>
#include <cstdint>

// ---------------------------------------------------------------------------
// GCN_VCG, round 4:
//  - GEMMs: persistent CTAs, resident weights in smem, M=64 tiles,
//    mma.sync bf16 3-pass float-split (Ah@Bh + Al@Bh + Ah@Bl), cp.async
//    double-buffered X prefetch (mlp kernel).
//  - Aggregation: CSR gather (warp per dst node), no atomics, no memsets.
// ---------------------------------------------------------------------------

#define D        128
#define NT       256
#define VMAX     50000
#define CMAX     210000
#define EHMAX    315000

// ------------------------- scratch (no runtime alloc) ----------------------
__device__ float g_t_pv2c[(size_t)VMAX * D];
__device__ float g_t_nv2c[(size_t)VMAX * D];
__device__ float g_t_pc2v[(size_t)CMAX * D];
__device__ float g_t_nc2v[(size_t)CMAX * D];
__device__ float g_agg_c[2][(size_t)CMAX * D];
__device__ float g_agg_v[2][(size_t)VMAX * D];
// weight images: per layer/chunk: [hi 32KB | lo 32KB], swizzled, smem-ready
__device__ unsigned char g_wimg_mlp[4][2 * 65536];
__device__ unsigned char g_wimg_cu[3 * 65536];
__device__ unsigned char g_wimg_vu[3 * 65536];
// CSR structures (iteration-invariant)
__device__ int   g_degi_pv[VMAX], g_degi_nv[VMAX];
__device__ int   g_degi_pc[CMAX], g_degi_nc[CMAX];
__device__ int   g_rp_pc[CMAX + 1], g_rp_nc[CMAX + 1];
__device__ int   g_rp_pv[VMAX + 1], g_rp_nv[VMAX + 1];
__device__ int   g_fl_pc[CMAX], g_fl_nc[CMAX], g_fl_pv[VMAX], g_fl_nv[VMAX];
__device__ int   g_sl_pc_src[EHMAX], g_sl_nc_src[EHMAX];
__device__ int   g_sl_pv_src[EHMAX], g_sl_nv_src[EHMAX];
__device__ float g_sl_pc_w[EHMAX], g_sl_nc_w[EHMAX];
__device__ float g_sl_pv_w[EHMAX], g_sl_nv_w[EHMAX];

// ------------------------------ helpers ------------------------------------
__device__ __forceinline__ uint32_t smem_u32(const void* p) {
    uint32_t a;
    asm("{ .reg .u64 t; cvta.to.shared.u64 t, %1; cvt.u32.u64 %0, t; }"
        : "=r"(a) : "l"(p));
    return a;
}

// byte offset of bf16 (row r, col c) in a [rows x 128] bf16 tile; 256B rows,
// 16B chunks XOR-swizzled by (r&7) for conflict-free ldmatrix.
__device__ __host__ __forceinline__ uint32_t swz(int r, int c) {
    return ((uint32_t)r << 8) + ((uint32_t)(((c >> 3) ^ (r & 7)) & 15) << 4)
         + ((uint32_t)(c & 7) << 1);
}

__device__ __forceinline__ void split2(float a, float b, uint32_t& hi, uint32_t& lo) {
    __nv_bfloat16 ha = __float2bfloat16(a);
    __nv_bfloat16 hb = __float2bfloat16(b);
    __nv_bfloat16 la = __float2bfloat16(a - __bfloat162float(ha));
    __nv_bfloat16 lb = __float2bfloat16(b - __bfloat162float(hb));
    hi = (uint32_t)__bfloat16_as_ushort(ha) | ((uint32_t)__bfloat16_as_ushort(hb) << 16);
    lo = (uint32_t)__bfloat16_as_ushort(la) | ((uint32_t)__bfloat16_as_ushort(lb) << 16);
}

__device__ __forceinline__ void ldm4(uint32_t addr, uint32_t& d0, uint32_t& d1,
                                     uint32_t& d2, uint32_t& d3) {
    asm volatile("ldmatrix.sync.aligned.m8n8.x4.shared.b16 {%0,%1,%2,%3}, [%4];"
                 : "=r"(d0), "=r"(d1), "=r"(d2), "=r"(d3) : "r"(addr));
}

__device__ __forceinline__ void mma16816(float* c, const uint32_t* a,
                                         const uint32_t* b) {
    asm volatile(
        "mma.sync.aligned.m16n8k16.row.col.f32.bf16.bf16.f32 "
        "{%0,%1,%2,%3}, {%4,%5,%6,%7}, {%8,%9}, {%0,%1,%2,%3};"
        : "+f"(c[0]), "+f"(c[1]), "+f"(c[2]), "+f"(c[3])
        : "r"(a[0]), "r"(a[1]), "r"(a[2]), "r"(a[3]), "r"(b[0]), "r"(b[1]));
}

__device__ __forceinline__ void cp16(uint32_t saddr, const void* g, bool pred) {
    int sz = pred ? 16 : 0;
    asm volatile("cp.async.cg.shared.global [%0], [%1], 16, %2;"
                 :: "r"(saddr), "l"(g), "r"(sz));
}
#define CP_COMMIT() asm volatile("cp.async.commit_group;" ::: "memory")
#define CP_WAIT0()  asm volatile("cp.async.wait_group 0;" ::: "memory")

// One K=128 GEMM pass: M=64 tile, 8 warps as 2m x 4n, warp tile 32x32.
// acc[s][nt][4]: s = 16-row block, nt = 8-col block. (frag recipes validated R3)
__device__ __forceinline__ void gemm_pass64(uint32_t sA, uint32_t sW,
                                            float acc[2][4][4],
                                            int wm, int wn, int lane) {
#pragma unroll
    for (int ks = 0; ks < 8; ks++) {
        const int kc = ks * 2;
        uint32_t a[2][4];
#pragma unroll
        for (int s = 0; s < 2; s++) {
            int row = wm * 32 + s * 16 + (lane & 7) + ((lane >> 3) & 1) * 8;
            int chunk = ((kc + (lane >> 4)) ^ (row & 7)) & 15;
            ldm4(sA + row * 256 + chunk * 16, a[s][0], a[s][1], a[s][2], a[s][3]);
        }
        uint32_t b[4][2];
#pragma unroll
        for (int p = 0; p < 2; p++) {
            int row = wn * 32 + p * 16 + (lane & 7) + (lane >> 4) * 8;
            int chunk = ((kc + ((lane >> 3) & 1)) ^ (row & 7)) & 15;
            ldm4(sW + row * 256 + chunk * 16,
                 b[2 * p][0], b[2 * p][1], b[2 * p + 1][0], b[2 * p + 1][1]);
        }
#pragma unroll
        for (int s = 0; s < 2; s++)
#pragma unroll
            for (int nt = 0; nt < 4; nt++)
                mma16816(acc[s][nt], a[s], b[nt]);
    }
}

__device__ __forceinline__ void zero_acc(float acc[2][4][4]) {
#pragma unroll
    for (int s = 0; s < 2; s++)
#pragma unroll
        for (int nt = 0; nt < 4; nt++)
#pragma unroll
            for (int j = 0; j < 4; j++) acc[s][nt][j] = 0.f;
}

// --------------------------- mlp2 persistent -------------------------------
// smem: [W0h W0l W1h W1l 128KB][Ahi 16KB][Alo 16KB][stage 2x32KB][bias 1KB]
#define MS_W    0
#define MS_AHI  131072
#define MS_ALO  147456
#define MS_ST   163840
#define MS_B    229376
#define MS_TOT  230400

extern "C" __global__ void __launch_bounds__(NT, 1)
mlp2_mma_kernel(const float* __restrict__ X, const uint4* __restrict__ Wimg,
                const float* __restrict__ bias, float* __restrict__ Y, int N) {
    extern __shared__ char sm[];
    const uint32_t sb = smem_u32(sm);
    const int tid = threadIdx.x, wid = tid >> 5, lane = tid & 31;
    const int wm = wid >> 2, wn = wid & 3;
    const int tiles = (N + 63) / 64;
    const int G = gridDim.x;
    float* bs = reinterpret_cast<float*>(sm + MS_B);

    // resident weights (both layers hi+lo, 128KB) via cp.async
#pragma unroll 4
    for (int i = tid; i < 8192; i += NT)
        cp16(sb + MS_W + i * 16, Wimg + i, true);
    if (tid < 2 * D) bs[tid] = bias[tid];

    // prefetch first tile's X into stage 0
    int t0 = blockIdx.x;
    if (t0 < tiles) {
        int row0 = t0 * 64;
#pragma unroll 4
        for (int i = tid; i < 2048; i += NT) {
            int r = i >> 5, c4 = i & 31, g = row0 + r;
            cp16(sb + MS_ST + i * 16, X + (size_t)g * D + c4 * 4, g < N);
        }
    }
    CP_COMMIT();
    CP_WAIT0();
    __syncthreads();

    int li = 0;
    for (int t = t0; t < tiles; t += G, li++) {
        const int row0 = t * 64;
        const uint32_t cur = sb + MS_ST + (li & 1) * 32768;
        const uint32_t nxt = sb + MS_ST + ((li + 1) & 1) * 32768;
        const float* curf = reinterpret_cast<const float*>(sm + (cur - sb));

        // prefetch next tile
        int tn = t + G;
        if (tn < tiles) {
            int rn0 = tn * 64;
#pragma unroll 4
            for (int i = tid; i < 2048; i += NT) {
                int r = i >> 5, c4 = i & 31, g = rn0 + r;
                cp16(nxt + i * 16, X + (size_t)g * D + c4 * 4, g < N);
            }
        }
        CP_COMMIT();

        // split stage fp32 -> A hi/lo bf16 tiles
#pragma unroll 4
        for (int i = tid; i < 2048; i += NT) {
            int r = i >> 5, c4 = i & 31;
            float4 x = *reinterpret_cast<const float4*>(curf + i * 4);
            uint32_t h0, l0, h1, l1;
            split2(x.x, x.y, h0, l0);
            split2(x.z, x.w, h1, l1);
            uint32_t off = swz(r, c4 * 4);
            *reinterpret_cast<uint2*>(sm + MS_AHI + off) = make_uint2(h0, h1);
            *reinterpret_cast<uint2*>(sm + MS_ALO + off) = make_uint2(l0, l1);
        }
        __syncthreads();

        float acc[2][4][4];
        zero_acc(acc);
        gemm_pass64(sb + MS_AHI, sb + MS_W,         acc, wm, wn, lane);
        gemm_pass64(sb + MS_ALO, sb + MS_W,         acc, wm, wn, lane);
        gemm_pass64(sb + MS_AHI, sb + MS_W + 32768, acc, wm, wn, lane);
        __syncthreads();

        // epilogue 1: bias + relu, split hidden back into A tiles
#pragma unroll
        for (int s = 0; s < 2; s++) {
#pragma unroll
            for (int nt = 0; nt < 4; nt++) {
                int m = wm * 32 + s * 16 + (lane >> 2);
                int n = wn * 32 + nt * 8 + (lane & 3) * 2;
                float b0 = bs[n], b1 = bs[n + 1];
                uint32_t h, l;
                float v0 = fmaxf(acc[s][nt][0] + b0, 0.f);
                float v1 = fmaxf(acc[s][nt][1] + b1, 0.f);
                split2(v0, v1, h, l);
                uint32_t off = swz(m, n);
                *reinterpret_cast<uint32_t*>(sm + MS_AHI + off) = h;
                *reinterpret_cast<uint32_t*>(sm + MS_ALO + off) = l;
                v0 = fmaxf(acc[s][nt][2] + b0, 0.f);
                v1 = fmaxf(acc[s][nt][3] + b1, 0.f);
                split2(v0, v1, h, l);
                off = swz(m + 8, n);
                *reinterpret_cast<uint32_t*>(sm + MS_AHI + off) = h;
                *reinterpret_cast<uint32_t*>(sm + MS_ALO + off) = l;
            }
        }
        __syncthreads();

        zero_acc(acc);
        gemm_pass64(sb + MS_AHI, sb + MS_W + 65536, acc, wm, wn, lane);
        gemm_pass64(sb + MS_ALO, sb + MS_W + 65536, acc, wm, wn, lane);
        gemm_pass64(sb + MS_AHI, sb + MS_W + 98304, acc, wm, wn, lane);

        // epilogue 2: bias + fp32 store
#pragma unroll
        for (int s = 0; s < 2; s++) {
#pragma unroll
            for (int nt = 0; nt < 4; nt++) {
                int m = wm * 32 + s * 16 + (lane >> 2);
                int n = wn * 32 + nt * 8 + (lane & 3) * 2;
                float b0 = bs[D + n], b1 = bs[D + n + 1];
                int g0 = row0 + m, g1 = row0 + m + 8;
                if (g0 < N) {
                    float2 o = make_float2(acc[s][nt][0] + b0, acc[s][nt][1] + b1);
                    *reinterpret_cast<float2*>(Y + (size_t)g0 * D + n) = o;
                }
                if (g1 < N) {
                    float2 o = make_float2(acc[s][nt][2] + b0, acc[s][nt][3] + b1);
                    *reinterpret_cast<float2*>(Y + (size_t)g1 * D + n) = o;
                }
            }
        }
        CP_WAIT0();
        __syncthreads();
    }
}

// --------------------------- update persistent -----------------------------
// smem: [W chunks 0..2 hi/lo 192KB][Ahi 16KB][Alo 16KB][bias 512B]
#define US_W    0
#define US_AHI  196608
#define US_ALO  212992
#define US_B    229376
#define US_TOT  229888

extern "C" __global__ void __launch_bounds__(NT, 1)
update_mma_kernel(const float* __restrict__ X0, const float* __restrict__ X1,
                  const float* __restrict__ X2, const uint4* __restrict__ Wimg,
                  const float* __restrict__ bias, float* __restrict__ Y, int N) {
    extern __shared__ char sm[];
    const uint32_t sb = smem_u32(sm);
    const int tid = threadIdx.x, wid = tid >> 5, lane = tid & 31;
    const int wm = wid >> 2, wn = wid & 3;
    const int tiles = (N + 63) / 64;
    const int G = gridDim.x;
    float* bs = reinterpret_cast<float*>(sm + US_B);

#pragma unroll 4
    for (int i = tid; i < 12288; i += NT)    // 192KB resident weights
        cp16(sb + US_W + i * 16, Wimg + i, true);
    if (tid < D) bs[tid] = bias[tid];
    CP_COMMIT();
    CP_WAIT0();
    __syncthreads();

    const float* srcs[3] = {X0, X1, X2};

    for (int t = blockIdx.x; t < tiles; t += G) {
        const int row0 = t * 64;
        float acc[2][4][4];
        zero_acc(acc);

#pragma unroll
        for (int s = 0; s < 3; s++) {
            const float* Xs = srcs[s];
#pragma unroll 4
            for (int i = tid; i < 2048; i += NT) {
                int r = i >> 5, c4 = i & 31, g = row0 + r;
                float4 x = make_float4(0.f, 0.f, 0.f, 0.f);
                if (g < N)
                    x = *reinterpret_cast<const float4*>(Xs + (size_t)g * D + c4 * 4);
                uint32_t h0, l0, h1, l1;
                split2(x.x, x.y, h0, l0);
                split2(x.z, x.w, h1, l1);
                uint32_t off = swz(r, c4 * 4);
                *reinterpret_cast<uint2*>(sm + US_AHI + off) = make_uint2(h0, h1);
                *reinterpret_cast<uint2*>(sm + US_ALO + off) = make_uint2(l0, l1);
            }
            __syncthreads();
            gemm_pass64(sb + US_AHI, sb + US_W + s * 65536,         acc, wm, wn, lane);
            gemm_pass64(sb + US_ALO, sb + US_W + s * 65536,         acc, wm, wn, lane);
            gemm_pass64(sb + US_AHI, sb + US_W + s * 65536 + 32768, acc, wm, wn, lane);
            __syncthreads();
        }

#pragma unroll
        for (int s = 0; s < 2; s++) {
#pragma unroll
            for (int nt = 0; nt < 4; nt++) {
                int m = wm * 32 + s * 16 + (lane >> 2);
                int n = wn * 32 + nt * 8 + (lane & 3) * 2;
                float b0 = bs[n], b1 = bs[n + 1];
                int g0 = row0 + m, g1 = row0 + m + 8;
                if (g0 < N) {
                    float2 o = make_float2(acc[s][nt][0] + b0, acc[s][nt][1] + b1);
                    *reinterpret_cast<float2*>(Y + (size_t)g0 * D + n) = o;
                }
                if (g1 < N) {
                    float2 o = make_float2(acc[s][nt][2] + b0, acc[s][nt][3] + b1);
                    *reinterpret_cast<float2*>(Y + (size_t)g1 * D + n) = o;
                }
            }
        }
    }
}

// ----------------------- weight image conversion ----------------------------
extern "C" __global__ void wconv_mlp_kernel(const float* __restrict__ W,
                                            unsigned char* __restrict__ img) {
    int t = blockIdx.x * blockDim.x + threadIdx.x;
    if (t >= 2 * 128 * 128) return;
    int l = t >> 14, k = (t >> 7) & 127, n = t & 127;
    float w = W[t];
    __nv_bfloat16 h = __float2bfloat16(w);
    __nv_bfloat16 lo = __float2bfloat16(w - __bfloat162float(h));
    unsigned char* base = img + (size_t)l * 65536;
    uint32_t off = swz(n, k);
    *reinterpret_cast<__nv_bfloat16*>(base + off) = h;
    *reinterpret_cast<__nv_bfloat16*>(base + 32768 + off) = lo;
}

extern "C" __global__ void wconv_upd_kernel(const float* __restrict__ W,
                                            unsigned char* __restrict__ img) {
    int t = blockIdx.x * blockDim.x + threadIdx.x;
    if (t >= 384 * 128) return;
    int k = t >> 7, n = t & 127;
    int s = k >> 7, kl = k & 127;
    float w = W[t];
    __nv_bfloat16 h = __float2bfloat16(w);
    __nv_bfloat16 lo = __float2bfloat16(w - __bfloat162float(h));
    unsigned char* base = img + (size_t)s * 65536;
    uint32_t off = swz(n, kl);
    *reinterpret_cast<__nv_bfloat16*>(base + off) = h;
    *reinterpret_cast<__nv_bfloat16*>(base + 32768 + off) = lo;
}

// ------------------------------ CSR build -----------------------------------
extern "C" __global__ void degree_kernel(const int* __restrict__ vE,
                                         const int* __restrict__ cE,
                                         const int* __restrict__ pE,
                                         const int* __restrict__ nE, int Eh) {
    int t = blockIdx.x * blockDim.x + threadIdx.x;
    if (t < Eh) {
        int e = pE[t];
        atomicAdd(&g_degi_pv[vE[e]], 1);
        atomicAdd(&g_degi_pc[cE[e]], 1);
    } else if (t < 2 * Eh) {
        int e = nE[t - Eh];
        atomicAdd(&g_degi_nv[vE[e]], 1);
        atomicAdd(&g_degi_nc[cE[e]], 1);
    }
}

// 4 exclusive scans, one block each (blockIdx selects array)
extern "C" __global__ void __launch_bounds__(1024)
scan4_kernel(int V, int C) {
    const int* d; int* r; int n;
    switch (blockIdx.x) {
        case 0:  d = g_degi_pc; r = g_rp_pc; n = C; break;
        case 1:  d = g_degi_nc; r = g_rp_nc; n = C; break;
        case 2:  d = g_degi_pv; r = g_rp_pv; n = V; break;
        default: d = g_degi_nv; r = g_rp_nv; n = V; break;
    }
    __shared__ int wsum[32];
    __shared__ int sh_carry, sh_total;
    int tid = threadIdx.x, lane = tid & 31, wid = tid >> 5;
    if (tid == 0) sh_carry = 0;
    __syncthreads();
    for (int base = 0; base < n; base += 1024) {
        int i = base + tid;
        int v = (i < n) ? d[i] : 0;
        int incl = v;
#pragma unroll
        for (int o = 1; o < 32; o <<= 1) {
            int x = __shfl_up_sync(0xffffffffu, incl, o);
            if (lane >= o) incl += x;
        }
        if (lane == 31) wsum[wid] = incl;
        __syncthreads();
        if (tid < 32) {
            int s = wsum[tid], ip = s;
#pragma unroll
            for (int o = 1; o < 32; o <<= 1) {
                int x = __shfl_up_sync(0xffffffffu, ip, o);
                if (tid >= o) ip += x;
            }
            wsum[tid] = ip - s;
            if (tid == 31) sh_total = ip;
        }
        __syncthreads();
        if (i < n) r[i] = sh_carry + wsum[wid] + incl - v;
        __syncthreads();
        if (tid == 0) sh_carry += sh_total;
        __syncthreads();
    }
    if (tid == 0) r[n] = sh_carry;
}

extern "C" __global__ void fill_kernel(const int* __restrict__ vE,
                                       const int* __restrict__ cE,
                                       const int* __restrict__ pE,
                                       const int* __restrict__ nE, int Eh) {
    int t = blockIdx.x * blockDim.x + threadIdx.x;
    if (t < Eh) {
        int e = pE[t];
        int v = vE[e], c = cE[e];
        float inv = rsqrtf((float)max(g_degi_pv[v], 1) * (float)max(g_degi_pc[c], 1));
        int pos = g_rp_pc[c] + atomicAdd(&g_fl_pc[c], 1);
        g_sl_pc_src[pos] = v;
        g_sl_pc_w[pos] = inv;
        int pos2 = g_rp_pv[v] + atomicAdd(&g_fl_pv[v], 1);
        g_sl_pv_src[pos2] = c;
        g_sl_pv_w[pos2] = inv;
    } else if (t < 2 * Eh) {
        int e = nE[t - Eh];
        int v = vE[e], c = cE[e];
        float inv = rsqrtf((float)max(g_degi_nv[v], 1) * (float)max(g_degi_nc[c], 1));
        int pos = g_rp_nc[c] + atomicAdd(&g_fl_nc[c], 1);
        g_sl_nc_src[pos] = v;
        g_sl_nc_w[pos] = inv;
        int pos2 = g_rp_nv[v] + atomicAdd(&g_fl_nv[v], 1);
        g_sl_nv_src[pos2] = c;
        g_sl_nv_w[pos2] = inv;
    }
}

// ------------------------------ CSR gather ----------------------------------
// one warp per destination node; lane covers a float4 chunk of the row
extern "C" __global__ void __launch_bounds__(NT)
gather_kernel(const float* __restrict__ src_mat, float* __restrict__ dst,
              const int* __restrict__ rp, const int* __restrict__ sl_src,
              const float* __restrict__ sl_w, int n) {
    long t = (long)blockIdx.x * blockDim.x + threadIdx.x;
    int node = (int)(t >> 5), lane = (int)(t & 31);
    if (node >= n) return;
    int j = rp[node], end = rp[node + 1];
    float4 acc = make_float4(0.f, 0.f, 0.f, 0.f);
    int s_next = 0; float w_next = 0.f;
    if (j < end) { s_next = __ldg(sl_src + j); w_next = __ldg(sl_w + j); }
    while (j < end) {
        int s = s_next; float w = w_next;
        j++;
        if (j < end) { s_next = __ldg(sl_src + j); w_next = __ldg(sl_w + j); }
        float4 x = __ldg(reinterpret_cast<const float4*>(src_mat + (size_t)s * D) + lane);
        acc.x = fmaf(w, x.x, acc.x);
        acc.y = fmaf(w, x.y, acc.y);
        acc.z = fmaf(w, x.z, acc.z);
        acc.w = fmaf(w, x.w, acc.w);
    }
    reinterpret_cast<float4*>(dst + (size_t)node * D)[lane] = acc;
}

// -------------------------------- launch ------------------------------------
extern "C" void kernel_launch(void* const* d_in, const int* in_sizes, int n_in,
                              void* d_out, int out_size) {
    int base = (n_in >= 20) ? 2 : 0;
    const int*   v_edge = (const int*)d_in[base + 0];
    const int*   c_edge = (const int*)d_in[base + 1];
    const int*   p_edge = (const int*)d_in[base + 2];
    const int*   n_edge = (const int*)d_in[base + 3];
    const float* v0     = (const float*)d_in[base + 4];
    const float* c0     = (const float*)d_in[base + 5];
    const float *Wm[4], *Bm[4];
    for (int i = 0; i < 4; i++) {
        Wm[i] = (const float*)d_in[base + 6 + 2 * i];
        Bm[i] = (const float*)d_in[base + 7 + 2 * i];
    }
    const float* cuW = (const float*)d_in[base + 14];
    const float* cub = (const float*)d_in[base + 15];
    const float* vuW = (const float*)d_in[base + 16];
    const float* vub = (const float*)d_in[base + 17];

    const int Eh = in_sizes[base + 2];
    const int V  = in_sizes[base + 4] / D;
    const int C  = in_sizes[base + 5] / D;

    void* p;
    float *t_pv2c, *t_nv2c, *t_pc2v, *t_nc2v, *agg_c, *agg_v;
    int *degi_pv, *degi_nv, *degi_pc, *degi_nc;
    int *rp_pc, *rp_nc, *rp_pv, *rp_nv;
    int *fl_pc, *fl_nc, *fl_pv, *fl_nv;
    int *sl_pc_s, *sl_nc_s, *sl_pv_s, *sl_nv_s;
    float *sl_pc_w, *sl_nc_w, *sl_pv_w, *sl_nv_w;
    unsigned char *img_mlp, *img_cu, *img_vu;
    cudaGetSymbolAddress(&p, g_t_pv2c); t_pv2c = (float*)p;
    cudaGetSymbolAddress(&p, g_t_nv2c); t_nv2c = (float*)p;
    cudaGetSymbolAddress(&p, g_t_pc2v); t_pc2v = (float*)p;
    cudaGetSymbolAddress(&p, g_t_nc2v); t_nc2v = (float*)p;
    cudaGetSymbolAddress(&p, g_agg_c);  agg_c  = (float*)p;
    cudaGetSymbolAddress(&p, g_agg_v);  agg_v  = (float*)p;
    cudaGetSymbolAddress(&p, g_degi_pv); degi_pv = (int*)p;
    cudaGetSymbolAddress(&p, g_degi_nv); degi_nv = (int*)p;
    cudaGetSymbolAddress(&p, g_degi_pc); degi_pc = (int*)p;
    cudaGetSymbolAddress(&p, g_degi_nc); degi_nc = (int*)p;
    cudaGetSymbolAddress(&p, g_rp_pc); rp_pc = (int*)p;
    cudaGetSymbolAddress(&p, g_rp_nc); rp_nc = (int*)p;
    cudaGetSymbolAddress(&p, g_rp_pv); rp_pv = (int*)p;
    cudaGetSymbolAddress(&p, g_rp_nv); rp_nv = (int*)p;
    cudaGetSymbolAddress(&p, g_fl_pc); fl_pc = (int*)p;
    cudaGetSymbolAddress(&p, g_fl_nc); fl_nc = (int*)p;
    cudaGetSymbolAddress(&p, g_fl_pv); fl_pv = (int*)p;
    cudaGetSymbolAddress(&p, g_fl_nv); fl_nv = (int*)p;
    cudaGetSymbolAddress(&p, g_sl_pc_src); sl_pc_s = (int*)p;
    cudaGetSymbolAddress(&p, g_sl_nc_src); sl_nc_s = (int*)p;
    cudaGetSymbolAddress(&p, g_sl_pv_src); sl_pv_s = (int*)p;
    cudaGetSymbolAddress(&p, g_sl_nv_src); sl_nv_s = (int*)p;
    cudaGetSymbolAddress(&p, g_sl_pc_w); sl_pc_w = (float*)p;
    cudaGetSymbolAddress(&p, g_sl_nc_w); sl_nc_w = (float*)p;
    cudaGetSymbolAddress(&p, g_sl_pv_w); sl_pv_w = (float*)p;
    cudaGetSymbolAddress(&p, g_sl_nv_w); sl_nv_w = (float*)p;
    cudaGetSymbolAddress(&p, g_wimg_mlp); img_mlp = (unsigned char*)p;
    cudaGetSymbolAddress(&p, g_wimg_cu);  img_cu  = (unsigned char*)p;
    cudaGetSymbolAddress(&p, g_wimg_vu);  img_vu  = (unsigned char*)p;

    float* agg_c_p = agg_c;
    float* agg_c_n = agg_c + (size_t)CMAX * D;
    float* agg_v_p = agg_v;
    float* agg_v_n = agg_v + (size_t)VMAX * D;

    float* outv = (float*)d_out;
    float* outc = outv + (size_t)4 * V * D;

    int sms = 148;
    cudaDeviceGetAttribute(&sms, cudaDevAttrMultiProcessorCount, 0);

    cudaFuncSetAttribute(mlp2_mma_kernel,
                         cudaFuncAttributeMaxDynamicSharedMemorySize, MS_TOT);
    cudaFuncSetAttribute(update_mma_kernel,
                         cudaFuncAttributeMaxDynamicSharedMemorySize, US_TOT);

    // ---- prep: degrees -> scan -> CSR fill; weight images ----
    cudaMemsetAsync(degi_pv, 0, (size_t)V * sizeof(int));
    cudaMemsetAsync(degi_nv, 0, (size_t)V * sizeof(int));
    cudaMemsetAsync(degi_pc, 0, (size_t)C * sizeof(int));
    cudaMemsetAsync(degi_nc, 0, (size_t)C * sizeof(int));
    cudaMemsetAsync(fl_pc, 0, (size_t)C * sizeof(int));
    cudaMemsetAsync(fl_nc, 0, (size_t)C * sizeof(int));
    cudaMemsetAsync(fl_pv, 0, (size_t)V * sizeof(int));
    cudaMemsetAsync(fl_nv, 0, (size_t)V * sizeof(int));
    {
        int blk = (2 * Eh + NT - 1) / NT;
        degree_kernel<<<blk, NT>>>(v_edge, c_edge, p_edge, n_edge, Eh);
        scan4_kernel<<<4, 1024>>>(V, C);
        fill_kernel<<<blk, NT>>>(v_edge, c_edge, p_edge, n_edge, Eh);
    }
    for (int i = 0; i < 4; i++)
        wconv_mlp_kernel<<<128, 256>>>(Wm[i], img_mlp + (size_t)i * 2 * 65536);
    wconv_upd_kernel<<<192, 256>>>(cuW, img_cu);
    wconv_upd_kernel<<<192, 256>>>(vuW, img_vu);

    cudaMemcpyAsync(outv, v0, (size_t)V * D * sizeof(float), cudaMemcpyDeviceToDevice);
    cudaMemcpyAsync(outc, c0, (size_t)C * D * sizeof(float), cudaMemcpyDeviceToDevice);

    const int gthC = (int)(((long)C * 32 + NT - 1) / NT);
    const int gthV = (int)(((long)V * 32 + NT - 1) / NT);

    for (int t = 0; t < 3; t++) {
        const float* vin = outv + (size_t)t * V * D;
        const float* cin = outc + (size_t)t * C * D;
        float* vout = outv + (size_t)(t + 1) * V * D;
        float* cout = outc + (size_t)(t + 1) * C * D;

        mlp2_mma_kernel<<<sms, NT, MS_TOT>>>(
            vin, (const uint4*)(img_mlp + 0 * 2 * 65536), Bm[0], t_pv2c, V);
        mlp2_mma_kernel<<<sms, NT, MS_TOT>>>(
            vin, (const uint4*)(img_mlp + 1 * 2 * 65536), Bm[1], t_nv2c, V);
        mlp2_mma_kernel<<<sms, NT, MS_TOT>>>(
            cin, (const uint4*)(img_mlp + 2 * 2 * 65536), Bm[2], t_pc2v, C);
        mlp2_mma_kernel<<<sms, NT, MS_TOT>>>(
            cin, (const uint4*)(img_mlp + 3 * 2 * 65536), Bm[3], t_nc2v, C);

        gather_kernel<<<gthC, NT>>>(t_pv2c, agg_c_p, rp_pc, sl_pc_s, sl_pc_w, C);
        gather_kernel<<<gthC, NT>>>(t_nv2c, agg_c_n, rp_nc, sl_nc_s, sl_nc_w, C);
        gather_kernel<<<gthV, NT>>>(t_pc2v, agg_v_p, rp_pv, sl_pv_s, sl_pv_w, V);
        gather_kernel<<<gthV, NT>>>(t_nc2v, agg_v_n, rp_nv, sl_nv_s, sl_nv_w, V);

        update_mma_kernel<<<sms, NT, US_TOT>>>(
            cin, agg_c_p, agg_c_n, (const uint4*)img_cu, cub, cout, C);
        update_mma_kernel<<<sms, NT, US_TOT>>>(
            vin, agg_v_p, agg_v_n, (const uint4*)img_vu, vub, vout, V);
    }
}